// round 4
// baseline (speedup 1.0000x reference)
#include <cuda_runtime.h>
#include <math_constants.h>

// Problem constants
#define D      768
#define NA     4096
#define NC     50000
#define NCEN   10000
#define TK     16
#define TKP    32          // partial top-k kept per split (slack for fp64 refine)

// top-k mining split
#define NSPLIT   16
#define CHUNK    (NC / NSPLIT)        // 3125
// centers split
#define NSPLIT_C 8
#define CHUNK_C  ((NCEN + NSPLIT_C - 1) / NSPLIT_C)  // 1250

// GEMM tiling
#define BM 64
#define BN 64
#define BK 16
#define BP 68          // padded shared stride

// top-k append buffer
#define CAP        96
#define COMPACT_AT 32

// ---- scratch (static __device__ globals: no runtime allocation) ----
__device__ float g_pv[NA * NSPLIT * TKP];      // partial topk values
__device__ int   g_pi[NA * NSPLIT * TKP];      // partial topk indices
__device__ int   g_ridx[NA * TKP];             // fp32 global top-32 indices (refine list)
__device__ float g_cmv[NA * NSPLIT_C * 2];     // partial center min-2 values
__device__ int   g_cmi[NA * NSPLIT_C * 2];     // partial center min-2 indices
__device__ float g_c2[NCEN];                   // ||center||^2 (fp32, pruning only)
__device__ int   g_fidx[NA * TK];              // final topk indices

__device__ __forceinline__ bool precede(float v1, int i1, float v2, int i2) {
    return (v1 > v2) || (v1 == v2 && i1 < i2);
}
__device__ __forceinline__ bool preceded(double v1, int i1, double v2, int i2) {
    return (v1 > v2) || (v1 == v2 && i1 < i2);
}

// ---------------------------------------------------------------------------
// ||center||^2 precompute (fp32, pruning pass only)
// ---------------------------------------------------------------------------
__global__ void k_c2(const float* __restrict__ cen) {
    int w = (blockIdx.x * blockDim.x + threadIdx.x) >> 5;
    int lane = threadIdx.x & 31;
    if (w >= NCEN) return;
    const float* p = cen + (size_t)w * D;
    float s = 0.f;
    for (int k = lane; k < D; k += 32) { float x = p[k]; s += x * x; }
    #pragma unroll
    for (int o = 16; o; o >>= 1) s += __shfl_down_sync(0xffffffffu, s, o);
    if (lane == 0) g_c2[w] = s;
}

// ---------------------------------------------------------------------------
// Candidates GEMM + fused per-row top-32 (partial over a column chunk)
// ---------------------------------------------------------------------------
__global__ __launch_bounds__(256)
void k_topk(const float* __restrict__ A, const float* __restrict__ Cand) {
    extern __shared__ float sm[];
    float* As     = sm;                         // [BK][BP]
    float* Bs     = As + BK * BP;               // [BK][BP]
    float* topv   = Bs + BK * BP;               // [BM][TKP]
    int*   topi   = (int*)(topv + BM * TKP);    // [BM][TKP]
    float* bufv   = (float*)(topi + BM * TKP);  // [BM][CAP]
    int*   bufi   = (int*)(bufv + BM * CAP);    // [BM][CAP]
    float* thresh = (float*)(bufi + BM * CAP);  // [BM]
    int*   cnt    = (int*)(thresh + BM);        // [BM]
    int*   nfill  = cnt + BM;                   // [BM]

    int tid = threadIdx.x;
    int rowBase = blockIdx.x * BM;
    int split = blockIdx.y;
    int colStart = split * CHUNK;
    int colEnd = colStart + CHUNK;

    if (tid < BM) { thresh[tid] = -CUDART_INF_F; cnt[tid] = 0; nfill[tid] = 0; }
    __syncthreads();

    int ty = tid >> 4, tx = tid & 15;
    int ldr = tid >> 2;
    int ldk = (tid & 3) * 4;

    int nT = (CHUNK + BN - 1) / BN;
    for (int t = 0; t < nT; t++) {
        int colBase = colStart + t * BN;
        float acc[4][4] = {};
        #pragma unroll 1
        for (int kt = 0; kt < D; kt += BK) {
            float4 av = *(const float4*)(A + (size_t)(rowBase + ldr) * D + kt + ldk);
            As[(ldk + 0) * BP + ldr] = av.x;
            As[(ldk + 1) * BP + ldr] = av.y;
            As[(ldk + 2) * BP + ldr] = av.z;
            As[(ldk + 3) * BP + ldr] = av.w;
            int gc = colBase + ldr;
            float4 bv4 = make_float4(0.f, 0.f, 0.f, 0.f);
            if (gc < colEnd) bv4 = *(const float4*)(Cand + (size_t)gc * D + kt + ldk);
            Bs[(ldk + 0) * BP + ldr] = bv4.x;
            Bs[(ldk + 1) * BP + ldr] = bv4.y;
            Bs[(ldk + 2) * BP + ldr] = bv4.z;
            Bs[(ldk + 3) * BP + ldr] = bv4.w;
            __syncthreads();
            #pragma unroll
            for (int kk = 0; kk < BK; kk++) {
                float4 a4 = *(const float4*)(As + kk * BP + ty * 4);
                float4 b4 = *(const float4*)(Bs + kk * BP + tx * 4);
                acc[0][0] += a4.x * b4.x; acc[0][1] += a4.x * b4.y;
                acc[0][2] += a4.x * b4.z; acc[0][3] += a4.x * b4.w;
                acc[1][0] += a4.y * b4.x; acc[1][1] += a4.y * b4.y;
                acc[1][2] += a4.y * b4.z; acc[1][3] += a4.y * b4.w;
                acc[2][0] += a4.z * b4.x; acc[2][1] += a4.z * b4.y;
                acc[2][2] += a4.z * b4.z; acc[2][3] += a4.z * b4.w;
                acc[3][0] += a4.w * b4.x; acc[3][1] += a4.w * b4.y;
                acc[3][2] += a4.w * b4.z; acc[3][3] += a4.w * b4.w;
            }
            __syncthreads();
        }
        #pragma unroll
        for (int i = 0; i < 4; i++) {
            int lr = ty * 4 + i;
            int grow = rowBase + lr;
            float th = thresh[lr];
            #pragma unroll
            for (int j = 0; j < 4; j++) {
                int gc = colBase + tx * 4 + j;
                float v = acc[i][j];
                if (gc < colEnd && gc != grow && v > th) {
                    int slot = atomicAdd(&cnt[lr], 1);
                    if (slot < CAP) { bufv[lr * CAP + slot] = v; bufi[lr * CAP + slot] = gc; }
                }
            }
        }
        __syncthreads();
        if (tid < BM) {
            int c = cnt[tid];
            if (c > 0 && (c >= COMPACT_AT || t == nT - 1)) {
                if (c > CAP) c = CAP;
                int nf = nfill[tid];
                float* tv = topv + tid * TKP;
                int*   ti = topi + tid * TKP;
                for (int s = 0; s < c; s++) {
                    float v = bufv[tid * CAP + s];
                    int gi = bufi[tid * CAP + s];
                    if (nf == TKP && !precede(v, gi, tv[TKP - 1], ti[TKP - 1])) continue;
                    int p = (nf < TKP) ? nf : TKP - 1;
                    while (p > 0 && precede(v, gi, tv[p - 1], ti[p - 1])) {
                        tv[p] = tv[p - 1]; ti[p] = ti[p - 1]; p--;
                    }
                    tv[p] = v; ti[p] = gi;
                    if (nf < TKP) nf++;
                }
                nfill[tid] = nf;
                cnt[tid] = 0;
                if (nf == TKP) thresh[tid] = tv[TKP - 1];
            }
        }
        __syncthreads();
    }
    if (tid < BM) {
        int row = rowBase + tid;
        int nf = nfill[tid];
        for (int k2 = 0; k2 < TKP; k2++) {
            g_pv[(row * NSPLIT + split) * TKP + k2] = (k2 < nf) ? topv[tid * TKP + k2] : -CUDART_INF_F;
            g_pi[(row * NSPLIT + split) * TKP + k2] = (k2 < nf) ? topi[tid * TKP + k2] : 0x7fffffff;
        }
    }
}

// ---------------------------------------------------------------------------
// Centers GEMM + fused min-2 of (c2 - 2*dot) per split (pruning pass)
// ---------------------------------------------------------------------------
__global__ __launch_bounds__(256)
void k_centers(const float* __restrict__ A, const float* __restrict__ Cen) {
    __shared__ float As[BK * BP];
    __shared__ float Bs[BK * BP];
    __shared__ float redv[BM * 32];
    __shared__ int   redi[BM * 32];

    int tid = threadIdx.x;
    int rowBase = blockIdx.x * BM;
    int split = blockIdx.y;
    int colStart = split * CHUNK_C;
    int colEnd = min(colStart + CHUNK_C, NCEN);

    int ty = tid >> 4, tx = tid & 15;
    int ldr = tid >> 2;
    int ldk = (tid & 3) * 4;

    float bv0[4], bv1[4]; int bi0[4], bi1[4];
    #pragma unroll
    for (int i = 0; i < 4; i++) {
        bv0[i] = bv1[i] = CUDART_INF_F;
        bi0[i] = bi1[i] = 0x7fffffff;
    }

    int nT = (colEnd - colStart + BN - 1) / BN;
    for (int t = 0; t < nT; t++) {
        int colBase = colStart + t * BN;
        float acc[4][4] = {};
        #pragma unroll 1
        for (int kt = 0; kt < D; kt += BK) {
            float4 av = *(const float4*)(A + (size_t)(rowBase + ldr) * D + kt + ldk);
            As[(ldk + 0) * BP + ldr] = av.x;
            As[(ldk + 1) * BP + ldr] = av.y;
            As[(ldk + 2) * BP + ldr] = av.z;
            As[(ldk + 3) * BP + ldr] = av.w;
            int gc = colBase + ldr;
            float4 cv4 = make_float4(0.f, 0.f, 0.f, 0.f);
            if (gc < colEnd) cv4 = *(const float4*)(Cen + (size_t)gc * D + kt + ldk);
            Bs[(ldk + 0) * BP + ldr] = cv4.x;
            Bs[(ldk + 1) * BP + ldr] = cv4.y;
            Bs[(ldk + 2) * BP + ldr] = cv4.z;
            Bs[(ldk + 3) * BP + ldr] = cv4.w;
            __syncthreads();
            #pragma unroll
            for (int kk = 0; kk < BK; kk++) {
                float4 a4 = *(const float4*)(As + kk * BP + ty * 4);
                float4 b4 = *(const float4*)(Bs + kk * BP + tx * 4);
                acc[0][0] += a4.x * b4.x; acc[0][1] += a4.x * b4.y;
                acc[0][2] += a4.x * b4.z; acc[0][3] += a4.x * b4.w;
                acc[1][0] += a4.y * b4.x; acc[1][1] += a4.y * b4.y;
                acc[1][2] += a4.y * b4.z; acc[1][3] += a4.y * b4.w;
                acc[2][0] += a4.z * b4.x; acc[2][1] += a4.z * b4.y;
                acc[2][2] += a4.z * b4.z; acc[2][3] += a4.z * b4.w;
                acc[3][0] += a4.w * b4.x; acc[3][1] += a4.w * b4.y;
                acc[3][2] += a4.w * b4.z; acc[3][3] += a4.w * b4.w;
            }
            __syncthreads();
        }
        #pragma unroll
        for (int j = 0; j < 4; j++) {
            int gc = colBase + tx * 4 + j;
            if (gc < colEnd) {
                float c2v = g_c2[gc];
                #pragma unroll
                for (int i = 0; i < 4; i++) {
                    float v = c2v - 2.0f * acc[i][j];
                    if (v < bv0[i] || (v == bv0[i] && gc < bi0[i])) {
                        bv1[i] = bv0[i]; bi1[i] = bi0[i];
                        bv0[i] = v; bi0[i] = gc;
                    } else if (v < bv1[i] || (v == bv1[i] && gc < bi1[i])) {
                        bv1[i] = v; bi1[i] = gc;
                    }
                }
            }
        }
    }
    #pragma unroll
    for (int i = 0; i < 4; i++) {
        redv[(ty * 4 + i) * 32 + tx * 2 + 0] = bv0[i];
        redi[(ty * 4 + i) * 32 + tx * 2 + 0] = bi0[i];
        redv[(ty * 4 + i) * 32 + tx * 2 + 1] = bv1[i];
        redi[(ty * 4 + i) * 32 + tx * 2 + 1] = bi1[i];
    }
    __syncthreads();
    if (tid < BM) {
        float b0 = CUDART_INF_F, b1 = CUDART_INF_F;
        int i0 = 0x7fffffff, i1 = 0x7fffffff;
        for (int x = 0; x < 32; x++) {
            float v = redv[tid * 32 + x]; int ii = redi[tid * 32 + x];
            if (v < b0 || (v == b0 && ii < i0)) { b1 = b0; i1 = i0; b0 = v; i0 = ii; }
            else if (v < b1 || (v == b1 && ii < i1)) { b1 = v; i1 = ii; }
        }
        int row = rowBase + tid;
        g_cmv[(row * NSPLIT_C + split) * 2 + 0] = b0;
        g_cmi[(row * NSPLIT_C + split) * 2 + 0] = i0;
        g_cmv[(row * NSPLIT_C + split) * 2 + 1] = b1;
        g_cmi[(row * NSPLIT_C + split) * 2 + 1] = i1;
    }
}

// ---------------------------------------------------------------------------
// Merge topk partials: bitonic sort of 512 pairs/row, keep fp32 top-32
// ---------------------------------------------------------------------------
__global__ void k_mtopk() {
    __shared__ float sv[512];
    __shared__ int   si[512];
    int row = blockIdx.x;
    int tid = threadIdx.x;
    sv[tid] = g_pv[row * 512 + tid];
    si[tid] = g_pi[row * 512 + tid];
    __syncthreads();
    for (int k = 2; k <= 512; k <<= 1) {
        for (int j = k >> 1; j > 0; j >>= 1) {
            int ixj = tid ^ j;
            if (ixj > tid) {
                float v1 = sv[tid], v2 = sv[ixj];
                int i1 = si[tid], i2 = si[ixj];
                bool desc = ((tid & k) == 0);
                bool sw = desc ? precede(v2, i2, v1, i1) : precede(v1, i1, v2, i2);
                if (sw) { sv[tid] = v2; si[tid] = i2; sv[ixj] = v1; si[ixj] = i1; }
            }
            __syncthreads();
        }
    }
    if (tid < TKP) g_ridx[row * TKP + tid] = si[tid];
}

// ---------------------------------------------------------------------------
// fp64 refine of top-32 sims -> exact top-16 (one block per anchor row)
// ---------------------------------------------------------------------------
__global__ __launch_bounds__(256)
void k_refine(const float* __restrict__ A, const float* __restrict__ Cand) {
    __shared__ double dv[TKP];
    __shared__ int    di[TKP];
    int row = blockIdx.x;
    int tid = threadIdx.x;
    int wid = tid >> 5, lane = tid & 31;
    const float* ar = A + (size_t)row * D;
    for (int c = wid; c < TKP; c += 8) {
        int idx = g_ridx[row * TKP + c];
        double s = 0.0;
        if (idx >= 0 && idx < NC) {
            const float* cr = Cand + (size_t)idx * D;
            for (int k = lane; k < D; k += 32)
                s += (double)ar[k] * (double)cr[k];
        } else {
            s = -CUDART_INF;
        }
        #pragma unroll
        for (int o = 16; o; o >>= 1) s += __shfl_down_sync(0xffffffffu, s, o);
        if (lane == 0) { dv[c] = s; di[c] = idx; }
    }
    __syncthreads();
    if (tid == 0) {
        double tv[TK]; int ti[TK]; int nf = 0;
        for (int s = 0; s < TKP; s++) {
            double v = dv[s]; int gi = di[s];
            if (nf == TK && !preceded(v, gi, tv[TK - 1], ti[TK - 1])) continue;
            int p = (nf < TK) ? nf : TK - 1;
            while (p > 0 && preceded(v, gi, tv[p - 1], ti[p - 1])) {
                tv[p] = tv[p - 1]; ti[p] = ti[p - 1]; p--;
            }
            tv[p] = v; ti[p] = gi;
            if (nf < TK) nf++;
        }
        for (int k2 = 0; k2 < TK; k2++) g_fidx[row * TK + k2] = ti[k2];
    }
}

// ---------------------------------------------------------------------------
// fp64 refine of 16 center candidates -> exact argmin + min_dist
// d2 computed as sum((a-c)^2) in fp64 (exact ranking)
// ---------------------------------------------------------------------------
__global__ __launch_bounds__(256)
void k_cenref(const float* __restrict__ A, const float* __restrict__ Cen,
              float* __restrict__ out) {
    __shared__ double dv[NSPLIT_C * 2];
    __shared__ int    di[NSPLIT_C * 2];
    int row = blockIdx.x;
    int tid = threadIdx.x;
    int wid = tid >> 5, lane = tid & 31;
    const float* ar = A + (size_t)row * D;
    for (int c = wid; c < NSPLIT_C * 2; c += 8) {
        int idx = g_cmi[row * NSPLIT_C * 2 + c];
        double s = CUDART_INF;
        if (idx >= 0 && idx < NCEN) {
            const float* cr = Cen + (size_t)idx * D;
            s = 0.0;
            for (int k = lane; k < D; k += 32) {
                double d = (double)ar[k] - (double)cr[k];
                s += d * d;
            }
        } else if (lane != 0) s = 0.0;
        #pragma unroll
        for (int o = 16; o; o >>= 1) s += __shfl_down_sync(0xffffffffu, s, o);
        if (lane == 0) { dv[c] = s; di[c] = idx; }
    }
    __syncthreads();
    if (tid == 0) {
        double best = CUDART_INF; int besti = 0x7fffffff;
        for (int s = 0; s < NSPLIT_C * 2; s++) {
            double v = dv[s]; int ii = di[s];
            if (v < best || (v == best && ii < besti)) { best = v; besti = ii; }
        }
        if (best < 0.0) best = 0.0;
        out[(size_t)NA * TK * D + row] = (float)besti;
        out[(size_t)NA * TK * D + NA + row] = (float)sqrt(best);
    }
}

// ---------------------------------------------------------------------------
// Gather: out[row][k][:] = candidates[idx][:]
// ---------------------------------------------------------------------------
__global__ void k_gather(const float* __restrict__ Cand, float* __restrict__ out) {
    int b = blockIdx.x;
    int t = threadIdx.x;
    int idx = g_fidx[b];
    const float4* c4 = (const float4*)(Cand + (size_t)idx * D);
    float4* o4 = (float4*)(out + (size_t)b * D);
    o4[t] = c4[t];
}

// ---------------------------------------------------------------------------
extern "C" void kernel_launch(void* const* d_in, const int* in_sizes, int n_in,
                              void* d_out, int out_size) {
    const float* A    = (const float*)d_in[0];   // anchors    [4096, 768]
    const float* Cand = (const float*)d_in[1];   // candidates [50000, 768]
    const float* Cen  = (const float*)d_in[2];   // centers    [10000, 768]
    float* out = (float*)d_out;

    int smem_topk = (2 * BK * BP + 2 * BM * TKP + 2 * BM * CAP + 3 * BM) * (int)sizeof(float);
    cudaFuncSetAttribute(k_topk, cudaFuncAttributeMaxDynamicSharedMemorySize, smem_topk);

    k_c2<<<(NCEN * 32 + 255) / 256, 256>>>(Cen);
    k_centers<<<dim3(NA / BM, NSPLIT_C), 256>>>(A, Cen);
    k_topk<<<dim3(NA / BM, NSPLIT), 256, smem_topk>>>(A, Cand);
    k_mtopk<<<NA, 512>>>();
    k_refine<<<NA, 256>>>(A, Cand);
    k_cenref<<<NA, 256>>>(A, Cen, out);
    k_gather<<<NA * TK, 192>>>(Cand, out);
}

// round 5
// speedup vs baseline: 5.5645x; 5.5645x over previous
#include <cuda_runtime.h>
#include <cuda_bf16.h>
#include <math_constants.h>
#include <stdint.h>

// Problem constants
#define D      768
#define NA     4096
#define NC     50000
#define NCEN   10000
#define TK     16
#define TKP    32          // kept per split (slack for fp64 refine)

// splits
#define NSPLIT   8
#define CHUNK    (NC / NSPLIT)        // 6250
#define NSPLIT_C 8
#define CHUNK_C  (NCEN / NSPLIT_C)    // 1250

// MMA tiling
#define BM 64
#define BN 128
#define BK 32
#define NKC (D / BK)       // 24 k-chunks
#define SAPAD 40           // bf16 elems per smem row (bank-conflict-free pad)
#define SBPAD 40

#define CAP 128            // per-tile append buffer = BN (cannot overflow)

// ---- scratch (static __device__ globals) ----
__device__ __align__(16) uint16_t g_Abf[NA * D];
__device__ __align__(16) uint16_t g_Candbf[(size_t)NC * D];
__device__ __align__(16) uint16_t g_Cenbf[NCEN * D];

__device__ float g_pv[NA * NSPLIT * TKP];
__device__ int   g_pi[NA * NSPLIT * TKP];
__device__ int   g_ridx[NA * TKP];
__device__ float g_cmv[NA * NSPLIT_C * 2];
__device__ int   g_cmi[NA * NSPLIT_C * 2];
__device__ float g_c2[NCEN];
__device__ int   g_fidx[NA * TK];

__device__ __forceinline__ bool precede(float v1, int i1, float v2, int i2) {
    return (v1 > v2) || (v1 == v2 && i1 < i2);
}
__device__ __forceinline__ bool preceded(double v1, int i1, double v2, int i2) {
    return (v1 > v2) || (v1 == v2 && i1 < i2);
}

__device__ __forceinline__ void mma16816(float* c, const uint32_t* a, const uint32_t* b) {
    asm volatile(
        "mma.sync.aligned.m16n8k16.row.col.f32.bf16.bf16.f32 "
        "{%0,%1,%2,%3}, {%4,%5,%6,%7}, {%8,%9}, {%0,%1,%2,%3};"
        : "+f"(c[0]), "+f"(c[1]), "+f"(c[2]), "+f"(c[3])
        : "r"(a[0]), "r"(a[1]), "r"(a[2]), "r"(a[3]), "r"(b[0]), "r"(b[1]));
}
__device__ __forceinline__ void cp16(uint32_t dst, const void* src, int sz) {
    asm volatile("cp.async.cg.shared.global [%0], [%1], 16, %2;"
                 :: "r"(dst), "l"(src), "r"(sz) : "memory");
}
__device__ __forceinline__ void cp_commit() {
    asm volatile("cp.async.commit_group;" ::: "memory");
}

// ---------------------------------------------------------------------------
// float -> bf16 conversion (vectorized)
// ---------------------------------------------------------------------------
__global__ void k_cvt(const float4* __restrict__ s, uint2* __restrict__ d, int n4) {
    int i = blockIdx.x * blockDim.x + threadIdx.x;
    if (i >= n4) return;
    float4 v = s[i];
    __nv_bfloat162 p0 = __floats2bfloat162_rn(v.x, v.y);
    __nv_bfloat162 p1 = __floats2bfloat162_rn(v.z, v.w);
    uint2 o;
    o.x = *(uint32_t*)&p0;
    o.y = *(uint32_t*)&p1;
    d[i] = o;
}

// ---------------------------------------------------------------------------
// ||center||^2 precompute (fp32, pruning only)
// ---------------------------------------------------------------------------
__global__ void k_c2(const float* __restrict__ cen) {
    int w = (blockIdx.x * blockDim.x + threadIdx.x) >> 5;
    int lane = threadIdx.x & 31;
    if (w >= NCEN) return;
    const float* p = cen + (size_t)w * D;
    float s = 0.f;
    for (int k = lane; k < D; k += 32) { float x = p[k]; s += x * x; }
    #pragma unroll
    for (int o = 16; o; o >>= 1) s += __shfl_down_sync(0xffffffffu, s, o);
    if (lane == 0) g_c2[w] = s;
}

// ---------------------------------------------------------------------------
// bf16 MMA GEMM + fused per-row top-32 (partial over a column chunk)
// grid (NA/BM, NSPLIT), 256 threads, dynamic smem
// ---------------------------------------------------------------------------
extern __shared__ __align__(16) char smraw[];

__global__ __launch_bounds__(256)
void k_topk(void) {
    uint16_t* As = (uint16_t*)smraw;                     // [2][64*SAPAD]
    uint16_t* Bs = As + 2 * 64 * SAPAD;                  // [2][128*SBPAD]
    float* topv   = (float*)(Bs + 2 * 128 * SBPAD);      // [BM][TKP]
    int*   topi   = (int*)(topv + BM * TKP);
    float* bufv   = (float*)(topi + BM * TKP);           // [BM][CAP]
    int*   bufi   = (int*)(bufv + BM * CAP);
    float* thresh = (float*)(bufi + BM * CAP);           // [BM]
    int*   cnt    = (int*)(thresh + BM);
    int*   nfill  = cnt + BM;

    int tid = threadIdx.x;
    int lane = tid & 31, wid = tid >> 5;
    int gid = lane >> 2, tig = lane & 3;
    int wm = wid & 1, wn = wid >> 1;     // warp covers rows wm*32.., cols wn*32..
    int ar = tid >> 2, aq = tid & 3;     // loader mapping

    int rowBase = blockIdx.x * BM;
    int split = blockIdx.y;
    int colStart = split * CHUNK;
    int colEnd = colStart + CHUNK;

    if (tid < BM) { thresh[tid] = -CUDART_INF_F; cnt[tid] = 0; nfill[tid] = 0; }
    __syncthreads();

    uint32_t sA = (uint32_t)__cvta_generic_to_shared(As);
    uint32_t sB = (uint32_t)__cvta_generic_to_shared(Bs);

    int nT = (CHUNK + BN - 1) / BN;
    for (int t = 0; t < nT; t++) {
        int colBase = colStart + t * BN;
        float c[2][4][4];
        #pragma unroll
        for (int i = 0; i < 2; i++)
            #pragma unroll
            for (int j = 0; j < 4; j++)
                #pragma unroll
                for (int f = 0; f < 4; f++) c[i][j][f] = 0.f;

        // ---- cp.async issue helper (stage st, k offset kt) ----
        auto issueAB = [&](int st, int kt) {
            uint32_t dstA = sA + (uint32_t)(st * 64 * SAPAD + ar * SAPAD + aq * 8) * 2;
            const uint16_t* srcA = g_Abf + (size_t)(rowBase + ar) * D + kt + aq * 8;
            cp16(dstA, srcA, 16);
            #pragma unroll
            for (int h = 0; h < 2; h++) {
                int r = ar + h * 64;
                int gc = colBase + r;
                bool ok = gc < colEnd;
                uint32_t dstB = sB + (uint32_t)(st * 128 * SBPAD + r * SBPAD + aq * 8) * 2;
                const uint16_t* srcB = g_Candbf + (size_t)(ok ? gc : 0) * D + kt + aq * 8;
                cp16(dstB, srcB, ok ? 16 : 0);
            }
            cp_commit();
        };

        issueAB(0, 0);
        for (int kk = 0; kk < NKC; kk++) {
            int cur = kk & 1;
            if (kk + 1 < NKC) {
                issueAB((kk + 1) & 1, (kk + 1) * BK);
                asm volatile("cp.async.wait_group 1;" ::: "memory");
            } else {
                asm volatile("cp.async.wait_group 0;" ::: "memory");
            }
            __syncthreads();
            const uint16_t* Ab = As + cur * 64 * SAPAD;
            const uint16_t* Bb = Bs + cur * 128 * SBPAD;
            #pragma unroll
            for (int ks = 0; ks < 2; ks++) {
                int k0 = ks * 16;
                uint32_t af[2][4], fb[4][2];
                #pragma unroll
                for (int i = 0; i < 2; i++) {
                    int r = wm * 32 + i * 16 + gid;
                    af[i][0] = *(const uint32_t*)(Ab + r * SAPAD + k0 + 2 * tig);
                    af[i][1] = *(const uint32_t*)(Ab + (r + 8) * SAPAD + k0 + 2 * tig);
                    af[i][2] = *(const uint32_t*)(Ab + r * SAPAD + k0 + 8 + 2 * tig);
                    af[i][3] = *(const uint32_t*)(Ab + (r + 8) * SAPAD + k0 + 8 + 2 * tig);
                }
                #pragma unroll
                for (int j = 0; j < 4; j++) {
                    int n = wn * 32 + j * 8 + gid;
                    fb[j][0] = *(const uint32_t*)(Bb + n * SBPAD + k0 + 2 * tig);
                    fb[j][1] = *(const uint32_t*)(Bb + n * SBPAD + k0 + 8 + 2 * tig);
                }
                #pragma unroll
                for (int i = 0; i < 2; i++)
                    #pragma unroll
                    for (int j = 0; j < 4; j++)
                        mma16816(c[i][j], af[i], fb[j]);
            }
            __syncthreads();
        }

        // ---- epilogue: append above-threshold candidates ----
        float th[4];
        #pragma unroll
        for (int i = 0; i < 2; i++)
            #pragma unroll
            for (int hi = 0; hi < 2; hi++)
                th[i * 2 + hi] = thresh[wm * 32 + i * 16 + hi * 8 + gid];

        #pragma unroll
        for (int i = 0; i < 2; i++) {
            #pragma unroll
            for (int f = 0; f < 4; f++) {
                int hi = f >> 1;
                int lr = wm * 32 + i * 16 + hi * 8 + gid;
                int grow = rowBase + lr;
                float thv = th[i * 2 + hi];
                #pragma unroll
                for (int j = 0; j < 4; j++) {
                    int gc = colBase + wn * 32 + j * 8 + 2 * tig + (f & 1);
                    float v = c[i][j][f];
                    if (gc < colEnd && gc != grow && v > thv) {
                        int slot = atomicAdd(&cnt[lr], 1);
                        if (slot < CAP) { bufv[lr * CAP + slot] = v; bufi[lr * CAP + slot] = gc; }
                    }
                }
            }
        }
        __syncthreads();
        // ---- compaction: one thread per row ----
        if (tid < BM) {
            int cc = cnt[tid];
            if (cc > 0) {
                if (cc > CAP) cc = CAP;
                int nf = nfill[tid];
                float* tv = topv + tid * TKP;
                int*   ti = topi + tid * TKP;
                for (int s = 0; s < cc; s++) {
                    float v = bufv[tid * CAP + s];
                    int gi = bufi[tid * CAP + s];
                    if (nf == TKP && !precede(v, gi, tv[TKP - 1], ti[TKP - 1])) continue;
                    int p = (nf < TKP) ? nf : TKP - 1;
                    while (p > 0 && precede(v, gi, tv[p - 1], ti[p - 1])) {
                        tv[p] = tv[p - 1]; ti[p] = ti[p - 1]; p--;
                    }
                    tv[p] = v; ti[p] = gi;
                    if (nf < TKP) nf++;
                }
                nfill[tid] = nf;
                cnt[tid] = 0;
                if (nf == TKP) thresh[tid] = tv[TKP - 1];
            }
        }
        __syncthreads();
    }
    if (tid < BM) {
        int row = rowBase + tid;
        int nf = nfill[tid];
        for (int k2 = 0; k2 < TKP; k2++) {
            g_pv[(row * NSPLIT + split) * TKP + k2] = (k2 < nf) ? topv[tid * TKP + k2] : -CUDART_INF_F;
            g_pi[(row * NSPLIT + split) * TKP + k2] = (k2 < nf) ? topi[tid * TKP + k2] : 0x7fffffff;
        }
    }
}

// ---------------------------------------------------------------------------
// bf16 MMA centers GEMM + fused min-2 of (c2 - 2*dot) per split
// grid (NA/BM, NSPLIT_C), 256 threads, static smem
// ---------------------------------------------------------------------------
__global__ __launch_bounds__(256)
void k_centers(void) {
    __shared__ __align__(16) uint16_t As[2 * 64 * SAPAD];
    __shared__ __align__(16) uint16_t Bs[2 * 128 * SBPAD];
    __shared__ float redv[BM * 32];
    __shared__ int   redi[BM * 32];

    int tid = threadIdx.x;
    int lane = tid & 31, wid = tid >> 5;
    int gid = lane >> 2, tig = lane & 3;
    int wm = wid & 1, wn = wid >> 1;
    int ar = tid >> 2, aq = tid & 3;

    int rowBase = blockIdx.x * BM;
    int split = blockIdx.y;
    int colStart = split * CHUNK_C;
    int colEnd = colStart + CHUNK_C;

    uint32_t sA = (uint32_t)__cvta_generic_to_shared(As);
    uint32_t sB = (uint32_t)__cvta_generic_to_shared(Bs);

    float bv0[4], bv1[4]; int bi0[4], bi1[4];
    #pragma unroll
    for (int i = 0; i < 4; i++) {
        bv0[i] = bv1[i] = CUDART_INF_F;
        bi0[i] = bi1[i] = 0x7fffffff;
    }

    int nT = (CHUNK_C + BN - 1) / BN;
    for (int t = 0; t < nT; t++) {
        int colBase = colStart + t * BN;
        float c[2][4][4];
        #pragma unroll
        for (int i = 0; i < 2; i++)
            #pragma unroll
            for (int j = 0; j < 4; j++)
                #pragma unroll
                for (int f = 0; f < 4; f++) c[i][j][f] = 0.f;

        auto issueAB = [&](int st, int kt) {
            uint32_t dstA = sA + (uint32_t)(st * 64 * SAPAD + ar * SAPAD + aq * 8) * 2;
            const uint16_t* srcA = g_Abf + (size_t)(rowBase + ar) * D + kt + aq * 8;
            cp16(dstA, srcA, 16);
            #pragma unroll
            for (int h = 0; h < 2; h++) {
                int r = ar + h * 64;
                int gc = colBase + r;
                bool ok = gc < colEnd;
                uint32_t dstB = sB + (uint32_t)(st * 128 * SBPAD + r * SBPAD + aq * 8) * 2;
                const uint16_t* srcB = g_Cenbf + (size_t)(ok ? gc : 0) * D + kt + aq * 8;
                cp16(dstB, srcB, ok ? 16 : 0);
            }
            cp_commit();
        };

        issueAB(0, 0);
        for (int kk = 0; kk < NKC; kk++) {
            int cur = kk & 1;
            if (kk + 1 < NKC) {
                issueAB((kk + 1) & 1, (kk + 1) * BK);
                asm volatile("cp.async.wait_group 1;" ::: "memory");
            } else {
                asm volatile("cp.async.wait_group 0;" ::: "memory");
            }
            __syncthreads();
            const uint16_t* Ab = As + cur * 64 * SAPAD;
            const uint16_t* Bb = Bs + cur * 128 * SBPAD;
            #pragma unroll
            for (int ks = 0; ks < 2; ks++) {
                int k0 = ks * 16;
                uint32_t af[2][4], fb[4][2];
                #pragma unroll
                for (int i = 0; i < 2; i++) {
                    int r = wm * 32 + i * 16 + gid;
                    af[i][0] = *(const uint32_t*)(Ab + r * SAPAD + k0 + 2 * tig);
                    af[i][1] = *(const uint32_t*)(Ab + (r + 8) * SAPAD + k0 + 2 * tig);
                    af[i][2] = *(const uint32_t*)(Ab + r * SAPAD + k0 + 8 + 2 * tig);
                    af[i][3] = *(const uint32_t*)(Ab + (r + 8) * SAPAD + k0 + 8 + 2 * tig);
                }
                #pragma unroll
                for (int j = 0; j < 4; j++) {
                    int n = wn * 32 + j * 8 + gid;
                    fb[j][0] = *(const uint32_t*)(Bb + n * SBPAD + k0 + 2 * tig);
                    fb[j][1] = *(const uint32_t*)(Bb + n * SBPAD + k0 + 8 + 2 * tig);
                }
                #pragma unroll
                for (int i = 0; i < 2; i++)
                    #pragma unroll
                    for (int j = 0; j < 4; j++)
                        mma16816(c[i][j], af[i], fb[j]);
            }
            __syncthreads();
        }

        // min-2 update
        #pragma unroll
        for (int i = 0; i < 2; i++)
            #pragma unroll
            for (int f = 0; f < 4; f++) {
                int ri = i * 2 + (f >> 1);
                #pragma unroll
                for (int j = 0; j < 4; j++) {
                    int gc = colBase + wn * 32 + j * 8 + 2 * tig + (f & 1);
                    if (gc < colEnd) {
                        float v = g_c2[gc] - 2.0f * c[i][j][f];
                        if (v < bv0[ri] || (v == bv0[ri] && gc < bi0[ri])) {
                            bv1[ri] = bv0[ri]; bi1[ri] = bi0[ri];
                            bv0[ri] = v; bi0[ri] = gc;
                        } else if (v < bv1[ri] || (v == bv1[ri] && gc < bi1[ri])) {
                            bv1[ri] = v; bi1[ri] = gc;
                        }
                    }
                }
            }
    }

    // reduction across the 16 thread-columns holding each row
    int sid = wn * 4 + tig;   // 0..15
    #pragma unroll
    for (int i = 0; i < 2; i++)
        #pragma unroll
        for (int hi = 0; hi < 2; hi++) {
            int ri = i * 2 + hi;
            int lr = wm * 32 + i * 16 + hi * 8 + gid;
            redv[lr * 32 + sid * 2 + 0] = bv0[ri];
            redi[lr * 32 + sid * 2 + 0] = bi0[ri];
            redv[lr * 32 + sid * 2 + 1] = bv1[ri];
            redi[lr * 32 + sid * 2 + 1] = bi1[ri];
        }
    __syncthreads();
    if (tid < BM) {
        float b0 = CUDART_INF_F, b1 = CUDART_INF_F;
        int i0 = 0x7fffffff, i1 = 0x7fffffff;
        for (int x = 0; x < 32; x++) {
            float v = redv[tid * 32 + x]; int ii = redi[tid * 32 + x];
            if (v < b0 || (v == b0 && ii < i0)) { b1 = b0; i1 = i0; b0 = v; i0 = ii; }
            else if (v < b1 || (v == b1 && ii < i1)) { b1 = v; i1 = ii; }
        }
        int row = rowBase + tid;
        g_cmv[(row * NSPLIT_C + split) * 2 + 0] = b0;
        g_cmi[(row * NSPLIT_C + split) * 2 + 0] = i0;
        g_cmv[(row * NSPLIT_C + split) * 2 + 1] = b1;
        g_cmi[(row * NSPLIT_C + split) * 2 + 1] = i1;
    }
}

// ---------------------------------------------------------------------------
// Merge topk partials: bitonic sort of 256 pairs/row, keep top-32
// ---------------------------------------------------------------------------
__global__ void k_mtopk() {
    __shared__ float sv[256];
    __shared__ int   si[256];
    int row = blockIdx.x;
    int tid = threadIdx.x;
    sv[tid] = g_pv[row * 256 + tid];
    si[tid] = g_pi[row * 256 + tid];
    __syncthreads();
    for (int k = 2; k <= 256; k <<= 1) {
        for (int j = k >> 1; j > 0; j >>= 1) {
            int ixj = tid ^ j;
            if (ixj > tid) {
                float v1 = sv[tid], v2 = sv[ixj];
                int i1 = si[tid], i2 = si[ixj];
                bool desc = ((tid & k) == 0);
                bool sw = desc ? precede(v2, i2, v1, i1) : precede(v1, i1, v2, i2);
                if (sw) { sv[tid] = v2; si[tid] = i2; sv[ixj] = v1; si[ixj] = i1; }
            }
            __syncthreads();
        }
    }
    if (tid < TKP) g_ridx[row * TKP + tid] = si[tid];
}

// ---------------------------------------------------------------------------
// fp64 refine of top-32 sims -> exact top-16 (one block per anchor row)
// ---------------------------------------------------------------------------
__global__ __launch_bounds__(256)
void k_refine(const float* __restrict__ A, const float* __restrict__ Cand) {
    __shared__ double dv[TKP];
    __shared__ int    di[TKP];
    int row = blockIdx.x;
    int tid = threadIdx.x;
    int wid = tid >> 5, lane = tid & 31;
    const float* ar = A + (size_t)row * D;
    for (int c = wid; c < TKP; c += 8) {
        int idx = g_ridx[row * TKP + c];
        double s = 0.0;
        if (idx >= 0 && idx < NC) {
            const float* cr = Cand + (size_t)idx * D;
            for (int k = lane; k < D; k += 32)
                s += (double)ar[k] * (double)cr[k];
        } else {
            s = -CUDART_INF;
        }
        #pragma unroll
        for (int o = 16; o; o >>= 1) s += __shfl_down_sync(0xffffffffu, s, o);
        if (lane == 0) { dv[c] = s; di[c] = idx; }
    }
    __syncthreads();
    if (tid == 0) {
        double tv[TK]; int ti[TK]; int nf = 0;
        for (int s = 0; s < TKP; s++) {
            double v = dv[s]; int gi = di[s];
            if (nf == TK && !preceded(v, gi, tv[TK - 1], ti[TK - 1])) continue;
            int p = (nf < TK) ? nf : TK - 1;
            while (p > 0 && preceded(v, gi, tv[p - 1], ti[p - 1])) {
                tv[p] = tv[p - 1]; ti[p] = ti[p - 1]; p--;
            }
            tv[p] = v; ti[p] = gi;
            if (nf < TK) nf++;
        }
        for (int k2 = 0; k2 < TK; k2++) g_fidx[row * TK + k2] = ti[k2];
    }
}

// ---------------------------------------------------------------------------
// fp64 refine of 16 center candidates -> exact argmin + min_dist
// ---------------------------------------------------------------------------
__global__ __launch_bounds__(256)
void k_cenref(const float* __restrict__ A, const float* __restrict__ Cen,
              float* __restrict__ out) {
    __shared__ double dv[NSPLIT_C * 2];
    __shared__ int    di[NSPLIT_C * 2];
    int row = blockIdx.x;
    int tid = threadIdx.x;
    int wid = tid >> 5, lane = tid & 31;
    const float* ar = A + (size_t)row * D;
    for (int c = wid; c < NSPLIT_C * 2; c += 8) {
        int idx = g_cmi[row * NSPLIT_C * 2 + c];
        double s = CUDART_INF;
        if (idx >= 0 && idx < NCEN) {
            const float* cr = Cen + (size_t)idx * D;
            s = 0.0;
            for (int k = lane; k < D; k += 32) {
                double d = (double)ar[k] - (double)cr[k];
                s += d * d;
            }
        } else if (lane != 0) s = 0.0;
        #pragma unroll
        for (int o = 16; o; o >>= 1) s += __shfl_down_sync(0xffffffffu, s, o);
        if (lane == 0) { dv[c] = s; di[c] = idx; }
    }
    __syncthreads();
    if (tid == 0) {
        double best = CUDART_INF; int besti = 0x7fffffff;
        for (int s = 0; s < NSPLIT_C * 2; s++) {
            double v = dv[s]; int ii = di[s];
            if (v < best || (v == best && ii < besti)) { best = v; besti = ii; }
        }
        if (best < 0.0) best = 0.0;
        out[(size_t)NA * TK * D + row] = (float)besti;
        out[(size_t)NA * TK * D + NA + row] = (float)sqrt(best);
    }
}

// ---------------------------------------------------------------------------
// Gather: out[row][k][:] = candidates[idx][:]
// ---------------------------------------------------------------------------
__global__ void k_gather(const float* __restrict__ Cand, float* __restrict__ out) {
    int b = blockIdx.x;
    int t = threadIdx.x;
    int idx = g_fidx[b];
    const float4* c4 = (const float4*)(Cand + (size_t)idx * D);
    float4* o4 = (float4*)(out + (size_t)b * D);
    o4[t] = c4[t];
}

// ---------------------------------------------------------------------------
extern "C" void kernel_launch(void* const* d_in, const int* in_sizes, int n_in,
                              void* d_out, int out_size) {
    const float* A    = (const float*)d_in[0];   // anchors    [4096, 768]
    const float* Cand = (const float*)d_in[1];   // candidates [50000, 768]
    const float* Cen  = (const float*)d_in[2];   // centers    [10000, 768]
    float* out = (float*)d_out;

    // dynamic smem for k_topk
    int smem_topk = (2 * 64 * SAPAD + 2 * 128 * SBPAD) * 2          // bf16 tiles
                  + (2 * BM * TKP + 2 * BM * CAP + 3 * BM) * 4;     // topk state
    cudaFuncSetAttribute(k_topk, cudaFuncAttributeMaxDynamicSharedMemorySize, smem_topk);

    // bf16 pointer resolution (device symbols)
    uint16_t *pAbf, *pCandbf, *pCenbf;
    cudaGetSymbolAddress((void**)&pAbf, g_Abf);
    cudaGetSymbolAddress((void**)&pCandbf, g_Candbf);
    cudaGetSymbolAddress((void**)&pCenbf, g_Cenbf);

    // 0) conversions to bf16
    k_cvt<<<(NA * D / 4 + 255) / 256, 256>>>((const float4*)A, (uint2*)pAbf, NA * D / 4);
    k_cvt<<<(NC * D / 4 + 255) / 256, 256>>>((const float4*)Cand, (uint2*)pCandbf, NC * D / 4);
    k_cvt<<<(NCEN * D / 4 + 255) / 256, 256>>>((const float4*)Cen, (uint2*)pCenbf, NCEN * D / 4);
    // 1) ||center||^2 (fp32)
    k_c2<<<(NCEN * 32 + 255) / 256, 256>>>(Cen);
    // 2) centers GEMM + min-2 pruning
    k_centers<<<dim3(NA / BM, NSPLIT_C), 256>>>();
    // 3) candidates GEMM + top-32 pruning
    k_topk<<<dim3(NA / BM, NSPLIT), 256, smem_topk>>>();
    // 4) merge partials -> refine list
    k_mtopk<<<NA, 256>>>();
    // 5) fp64 exact top-16
    k_refine<<<NA, 256>>>(A, Cand);
    // 6) fp64 exact argmin + min_dist
    k_cenref<<<NA, 256>>>(A, Cen, out);
    // 7) gather hard negatives
    k_gather<<<NA * TK, 192>>>(Cand, out);
}